// round 13
// baseline (speedup 1.0000x reference)
#include <cuda_runtime.h>
#include <cuda_fp16.h>
#include <cstdint>

// NCC loss, sliding-window, 4 px/thread, hybrid register/smem ring, occ-7.
//
// Block: 64 threads = 2 independent warps; warp owns a 128-px-wide, HS=32-row
// strip (40 row pushes); thread owns 4 adjacent x outputs. Per input row:
//   - row segments (136 floats of I and J incl. x-halo) land in a warp-private
//     4-deep smem staging ring via cp.async.cg 16B (zero-fill OOB chunks);
//     distance-3 prefetch, wait_group 3, __syncwarp only.
//   - 9-tap horizontal sums of 5 channels for 4 px from 3+3 LDS.128 via the
//     shared-core scheme (core = taps 3..8).
//   - vertical 9-row sliding sums, 9-deep ring, HYBRID storage:
//       channels I, J      -> REGISTERS (9 x 2 u32 each, static indices)
//       channels I2,J2,IJ  -> smem (8B = 2 x half2 per entry, LDS.64/STS.64)
//     run (packed f32x2 per pixel-pair) adds fp32 h, subtracts the
//     half-rounded value 9 rows later (RN noise cancels in the mean).
//   - emit: packed-f32x2 cc per pixel-pair; fractions grouped over 4 rows
//     -> one rcp.approx per 8 px.
// 1024 blocks x 22.6 KB smem, regs<=146 -> 7 blocks/SM: single wave, all
// warps resident. Finalize fused via double atomicAdd + arrival counter.

#define IMG   1024
#define NB    8
#define HS    32
#define TPB   64
#define NWB   2
#define NPUSH (HS + 8)        // 40 = 4 + 4*9
#define SEGF  136             // floats staged per warp-row per array
#define NBUF  4               // staging ring depth (distance-3 prefetch)
#define RSLOT 9
#define NSC   3               // smem ring channels (I2, J2, IJ)
#define GX    4               // 4 x (2 warps x 128 px) = 1024
#define GY    (IMG / HS)      // 32
#define NBLK  (GX * GY * NB)  // 1024

// dynamic smem:
//   [0, STG)        staging: [buf][warp][arr][SEGF] floats     (8704 B)
//   [STG, +RING)    ring:    [slot][ch(3)][tid] 8B entries     (13824 B)
//   tail            warpsum[2]
#define STG_FLOATS (NBUF * NWB * 2 * SEGF)                 // 2176
#define RING_U64   (RSLOT * NSC * TPB)                     // 1728
#define SMEM_BYTES ((STG_FLOATS + 2 * RING_U64 + 2) * 4)   // 22536 B

typedef unsigned long long ull;

__device__ double       g_accum;
__device__ unsigned int g_cnt;

__device__ __forceinline__ ull pk2(float lo, float hi) {
    ull o;
    asm("mov.b64 %0, {%1, %2};" : "=l"(o)
        : "r"(__float_as_uint(lo)), "r"(__float_as_uint(hi)));
    return o;
}
__device__ __forceinline__ float2 upk2(ull v) {
    unsigned a, b;
    asm("mov.b64 {%0, %1}, %2;" : "=r"(a), "=r"(b) : "l"(v));
    return make_float2(__uint_as_float(a), __uint_as_float(b));
}
#define FADD2(o,a,b)   asm("add.rn.f32x2 %0,%1,%2;"    : "=l"(o) : "l"(a), "l"(b))
#define FMUL2(o,a,b)   asm("mul.rn.f32x2 %0,%1,%2;"    : "=l"(o) : "l"(a), "l"(b))
#define FFMA2(o,a,b,c) asm("fma.rn.f32x2 %0,%1,%2,%3;" : "=l"(o) : "l"(a), "l"(b), "l"(c))

__device__ __forceinline__ void cp16(uint32_t dst, const float* src, uint32_t sz) {
    asm volatile("cp.async.cg.shared.global [%0], [%1], 16, %2;"
                 :: "r"(dst), "l"(src), "r"(sz));
}
#define CP_COMMIT() asm volatile("cp.async.commit_group;" ::: "memory")
#define CP_WAIT3()  asm volatile("cp.async.wait_group 3;" ::: "memory")

__global__ __launch_bounds__(TPB, 7) void ncc_main_kernel(
    const float* __restrict__ I, const float* __restrict__ J,
    float* __restrict__ out)
{
    extern __shared__ __align__(16) float dyn[];
    float* warpsum = dyn + STG_FLOATS + 2 * RING_U64;

    const int tid  = threadIdx.x;
    const int lane = tid & 31;
    const int w    = tid >> 5;
    const int W0   = blockIdx.x * 256 + w * 128;
    const int Y0   = blockIdx.y * HS;
    const size_t imgoff = (size_t)blockIdx.z * IMG * IMG;

    uint32_t smem_u32;
    asm("{ .reg .u64 t; cvta.to.shared.u64 t, %1; cvt.u32.u64 %0, t; }"
        : "=r"(smem_u32) : "l"(dyn));

    // ---- cp.async chunk assignment: 34 float4 chunks per array per warp-row
    // (floats [W0-4, W0+132)); 68 chunks total across I then J.
    const int  cA   = lane;            // I chunks 0..31
    const int  gxA  = W0 - 4 + 4 * cA;
    const bool vAok = (gxA >= 0) && (gxA <= IMG - 4);
    const float* pbaseA = I + imgoff + (vAok ? gxA : 0);
    const uint32_t dstA0 = smem_u32 + ((w * 2 + 0) * SEGF + 4 * cA) * 4;

    const bool bIsI = lane < 2;        // chunks 32,33 are I; then J 0..29
    const int  cB   = bIsI ? (32 + lane) : (lane - 2);
    const int  gxB  = W0 - 4 + 4 * cB;
    const bool vBok = (gxB >= 0) && (gxB <= IMG - 4);
    const float* pbaseB = (bIsI ? I : J) + imgoff + (vBok ? gxB : 0);
    const uint32_t dstB0 = smem_u32 + ((w * 2 + (bIsI ? 0 : 1)) * SEGF + 4 * cB) * 4;

    const bool hasC = lane < 4;        // J chunks 30..33
    const int  cC   = 30 + lane;
    const int  gxC  = W0 - 4 + 4 * cC;
    const bool vCok = (gxC >= 0) && (gxC <= IMG - 4);
    const float* pbaseC = J + imgoff + (vCok ? gxC : 0);
    const uint32_t dstC0 = smem_u32 + ((w * 2 + 1) * SEGF + 4 * cC) * 4;

    const uint32_t BUFSTRIDE = NWB * 2 * SEGF * 4;   // 2176 bytes

    // ---- smem ring base (channels 2..4), 8B entry = 4 px as 2 x half2
    ull* ringT = (ull*)(dyn + STG_FLOATS) + tid;
#pragma unroll
    for (int s = 0; s < RSLOT; s++)
#pragma unroll
        for (int c = 0; c < NSC; c++)
            ringT[(s * NSC + c) * TPB] = 0ull;

    // ---- register ring (channels 0,1 = I, J): static indices only
    uint32_t rgl[2][RSLOT], rgh[2][RSLOT];
#pragma unroll
    for (int s = 0; s < RSLOT; s++) {
        rgl[0][s] = 0u; rgh[0][s] = 0u;
        rgl[1][s] = 0u; rgh[1][s] = 0u;
    }

    // ---- constants / state
    const ull NEG1   = pk2(-1.0f, -1.0f);
    const ull MINV81 = pk2(-1.0f / 81.0f, -1.0f / 81.0f);
    const ull EPS2   = pk2(1e-5f, 1e-5f);
    ull run[5][2];                        // [channel][pixel-pair]
#pragma unroll
    for (int c = 0; c < 5; c++) { run[c][0] = 0ull; run[c][1] = 0ull; }

    float acc = 0.f;
    float gn[2] = {0.f, 0.f}, gd[2] = {1.f, 1.f};

    // ---- stage: push rr -> input row Y0-4+rr (clamped addr, zero-fill OOB)
    auto stage = [&](int rr) {
        const int yin  = Y0 - 4 + rr;
        const bool yok = (unsigned)yin < (unsigned)IMG;
        const int  yc  = min(max(yin, 0), IMG - 1);
        const uint32_t off  = (uint32_t)yc << 10;
        const uint32_t boff = (uint32_t)(rr & (NBUF - 1)) * BUFSTRIDE;
        cp16(dstA0 + boff, pbaseA + off, (yok && vAok) ? 16u : 0u);
        cp16(dstB0 + boff, pbaseB + off, (yok && vBok) ? 16u : 0u);
        if (hasC)
            cp16(dstC0 + boff, pbaseC + off, (yok && vCok) ? 16u : 0u);
        CP_COMMIT();
    };

    // ---- per-push body; slot is a compile-time constant at every call site
    auto body = [&](int r, int slot, bool emitOK) {
        if (r + 3 < NPUSH) stage(r + 3);
        else               CP_COMMIT();
        CP_WAIT3();
        __syncwarp();

        // 12-float windows (4 px) from 3 LDS.128 per array
        const int buf = r & (NBUF - 1);
        const float4* fI4 = (const float4*)(dyn + (buf * NWB + w) * 2 * SEGF);
        const float4* fJ4 = fI4 + SEGF / 4;
        float4 ia = fI4[lane], ib = fI4[lane + 1], ic = fI4[lane + 2];
        float4 ja = fJ4[lane], jb = fJ4[lane + 1], jc = fJ4[lane + 2];
        float vi[12] = {ia.x, ia.y, ia.z, ia.w, ib.x, ib.y,
                        ib.z, ib.w, ic.x, ic.y, ic.z, ic.w};
        float vj[12] = {ja.x, ja.y, ja.z, ja.w, jb.x, jb.y,
                        jb.z, jb.w, jc.x, jc.y, jc.z, jc.w};

        // shared-core horizontal 9-tap sums for 4 px
        float h[5][4];
#pragma unroll
        for (int c = 0; c < 5; c++) {
            auto tap = [&](int k) -> float {
                return (c == 0) ? vi[k]
                     : (c == 1) ? vj[k]
                     : (c == 2) ? vi[k] * vi[k]
                     : (c == 3) ? vj[k] * vj[k]
                                : vi[k] * vj[k];
            };
            float core = tap(3) + tap(4) + tap(5) + tap(6) + tap(7) + tap(8);
            float m01  = core + tap(1) + tap(2);
            float m23  = core + tap(9) + tap(10);
            h[c][0] = m01 + tap(0);
            h[c][1] = m01 + tap(9);
            h[c][2] = m23 + tap(2);
            h[c][3] = m23 + tap(11);
        }

        // run update shared by both ring kinds
        auto upd = [&](int c, uint32_t olo, uint32_t ohi) {
            float2 o01 = __half22float2(*(__half2*)&olo);
            float2 o23 = __half22float2(*(__half2*)&ohi);
            ull od0 = pk2(o01.x, o01.y);
            ull od1 = pk2(o23.x, o23.y);
            ull h01 = pk2(h[c][0], h[c][1]);
            ull h23 = pk2(h[c][2], h[c][3]);
            FADD2(run[c][0], run[c][0], h01);
            FFMA2(run[c][0], od0, NEG1, run[c][0]);
            FADD2(run[c][1], run[c][1], h23);
            FFMA2(run[c][1], od1, NEG1, run[c][1]);
        };

        // channels 0,1: register ring (slot literal -> regs)
#pragma unroll
        for (int c = 0; c < 2; c++) {
            uint32_t olo = rgl[c][slot], ohi = rgh[c][slot];
            __half2 nlo = __floats2half2_rn(h[c][0], h[c][1]);
            __half2 nhi = __floats2half2_rn(h[c][2], h[c][3]);
            rgl[c][slot] = *(uint32_t*)&nlo;
            rgh[c][slot] = *(uint32_t*)&nhi;
            upd(c, olo, ohi);
        }
        // channels 2..4: smem ring
#pragma unroll
        for (int c = 2; c < 5; c++) {
            ull* rp  = ringT + (slot * NSC + (c - 2)) * TPB;
            ull  old = *rp;                               // LDS.64
            __half2 nlo = __floats2half2_rn(h[c][0], h[c][1]);
            __half2 nhi = __floats2half2_rn(h[c][2], h[c][3]);
            ull nw;
            asm("mov.b64 %0, {%1, %2};" : "=l"(nw)
                : "r"(*(uint32_t*)&nlo), "r"(*(uint32_t*)&nhi));
            *rp = nw;                                     // STS.64
            uint32_t olo, ohi;
            asm("mov.b64 {%0, %1}, %2;" : "=r"(olo), "=r"(ohi) : "l"(old));
            upd(c, olo, ohi);
        }

        // emit output row oy = Y0 + (r - 8)
        if (emitOK) {
            const int cnt = (r - 8) & 3;
#pragma unroll
            for (int p = 0; p < 2; p++) {
                ull t, u, cross2, iv2, jv2, n2, d2;
                FMUL2(t, run[0][p], MINV81);              // -si/81
                FFMA2(cross2, t, run[1][p], run[4][p]);   // SIJ - si*sj/81
                FFMA2(iv2,    t, run[0][p], run[2][p]);   // SI2 - si^2/81
                FMUL2(u, run[1][p], MINV81);              // -sj/81
                FFMA2(jv2,    u, run[1][p], run[3][p]);   // SJ2 - sj^2/81
                FMUL2(n2, cross2, cross2);
                FFMA2(d2, iv2, jv2, EPS2);
                float2 n = upk2(n2), d = upk2(d2);
                float rowN = fmaf(n.x, d.y, n.y * d.x);
                float rowD = d.x * d.y;
                if (cnt == 0) { gn[p] = rowN; gd[p] = rowD; }
                else { gn[p] = fmaf(gn[p], rowD, rowN * gd[p]); gd[p] *= rowD; }
                if (cnt == 3) {
                    float rc;
                    asm("rcp.approx.f32 %0, %1;" : "=f"(rc) : "f"(gd[p]));
                    acc = fmaf(gn[p], rc, acc);
                }
            }
        }
    };

    // ---- prologue: fill pipeline 3 deep, peel pushes 0..3 (slots 0..3)
    stage(0); stage(1); stage(2);
    body(0, 0, false);
    body(1, 1, false);
    body(2, 2, false);
    body(3, 3, false);

    // ---- main: 4 x unroll-9; slot = (4+s) % 9 compile-time
#pragma unroll 1
    for (int m = 0; m < 4; m++) {
#pragma unroll
        for (int s = 0; s < 9; s++) {
            const int r = 4 + 9 * m + s;
            const bool emitOK = (s >= 4) ? true : (m > 0);
            body(r, (4 + s) % 9, emitOK);
        }
    }

    // ---- block reduction (2 warps) + fused finalize
#pragma unroll
    for (int off = 16; off > 0; off >>= 1)
        acc += __shfl_down_sync(0xFFFFFFFFu, acc, off);
    if (lane == 0) warpsum[w] = acc;
    __syncthreads();
    if (tid == 0) {
        float v = warpsum[0] + warpsum[1];
        atomicAdd(&g_accum, (double)v);
        __threadfence();
        unsigned prev = atomicAdd(&g_cnt, 1u);
        if (prev == NBLK - 1) {               // last block finalizes + resets
            double tot = atomicAdd(&g_accum, 0.0);
            out[0] = (float)(tot / (double)((size_t)NB * IMG * IMG));
            g_accum = 0.0;
            g_cnt   = 0u;
        }
    }
}

extern "C" void kernel_launch(void* const* d_in, const int* in_sizes, int n_in,
                              void* d_out, int out_size) {
    const float* I = (const float*)d_in[0];
    const float* J = (const float*)d_in[1];
    float* out = (float*)d_out;

    cudaFuncSetAttribute(ncc_main_kernel,
                         cudaFuncAttributeMaxDynamicSharedMemorySize, SMEM_BYTES);
    dim3 grid(GX, GY, NB);
    ncc_main_kernel<<<grid, TPB, SMEM_BYTES>>>(I, J, out);
}

// round 15
// speedup vs baseline: 1.5137x; 1.5137x over previous
#include <cuda_runtime.h>
#include <cuda_fp16.h>
#include <cstdint>

// NCC loss, sliding-window, 4 px/thread, hybrid register/smem ring,
// TPB=128 geometry (R10) + deep cp.async pipeline (R8) + hybrid ring (R11).
//
// Block: 128 threads = 4 independent warps; warp owns a 128-px-wide, HS=32-row
// strip (40 row pushes); thread owns 4 adjacent x outputs. Per input row:
//   - row segments (136 floats of I and J incl. x-halo) land in a warp-private
//     4-deep smem staging ring via cp.async.cg 16B (zero-fill OOB chunks);
//     distance-3 prefetch, wait_group 3, __syncwarp only.
//   - 9-tap horizontal sums of 5 channels for 4 px from 3+3 LDS.128 via the
//     shared-core scheme (core = taps 3..8).
//   - vertical 9-row sliding sums, 9-deep ring, HYBRID storage:
//       channels I, J      -> REGISTERS (9 x 2 u32 each, static indices)
//       channels I2,J2,IJ  -> smem (8B = 2 x half2 per entry, LDS.64/STS.64)
//     run (packed f32x2 per pixel-pair) adds fp32 h, subtracts the
//     half-rounded value 9 rows later (RN noise cancels in the mean).
//   - emit: packed-f32x2 cc per pixel-pair; fractions grouped over 4 rows
//     -> one rcp.approx per 8 px.
// 512 blocks x 45.1 KB smem, regs<=128 -> 4 blocks/SM; grid 3.46 blocks/SM
// so effectively single wave. Finalize fused via double atomicAdd + counter.

#define IMG   1024
#define NB    8
#define HS    32
#define TPB   128
#define NWB   4
#define NPUSH (HS + 8)        // 40 = 4 + 4*9
#define SEGF  136             // floats staged per warp-row per array
#define NBUF  4               // staging ring depth (distance-3 prefetch)
#define RSLOT 9
#define NSC   3               // smem ring channels (I2, J2, IJ)
#define GX    2               // 2 x (4 warps x 128 px) = 1024
#define GY    (IMG / HS)      // 32
#define NBLK  (GX * GY * NB)  // 512

// dynamic smem:
//   [0, STG)        staging: [buf][warp][arr][SEGF] floats     (17408 B)
//   [STG, +RING)    ring:    [slot][ch(3)][tid] 8B entries     (27648 B)
//   tail            warpsum[4]
#define STG_FLOATS (NBUF * NWB * 2 * SEGF)                 // 4352
#define RING_U64   (RSLOT * NSC * TPB)                     // 3456
#define SMEM_BYTES ((STG_FLOATS + 2 * RING_U64 + 4) * 4)   // 45072 B

typedef unsigned long long ull;

__device__ double       g_accum;
__device__ unsigned int g_cnt;

__device__ __forceinline__ ull pk2(float lo, float hi) {
    ull o;
    asm("mov.b64 %0, {%1, %2};" : "=l"(o)
        : "r"(__float_as_uint(lo)), "r"(__float_as_uint(hi)));
    return o;
}
__device__ __forceinline__ float2 upk2(ull v) {
    unsigned a, b;
    asm("mov.b64 {%0, %1}, %2;" : "=r"(a), "=r"(b) : "l"(v));
    return make_float2(__uint_as_float(a), __uint_as_float(b));
}
#define FADD2(o,a,b)   asm("add.rn.f32x2 %0,%1,%2;"    : "=l"(o) : "l"(a), "l"(b))
#define FMUL2(o,a,b)   asm("mul.rn.f32x2 %0,%1,%2;"    : "=l"(o) : "l"(a), "l"(b))
#define FFMA2(o,a,b,c) asm("fma.rn.f32x2 %0,%1,%2,%3;" : "=l"(o) : "l"(a), "l"(b), "l"(c))

__device__ __forceinline__ void cp16(uint32_t dst, const float* src, uint32_t sz) {
    asm volatile("cp.async.cg.shared.global [%0], [%1], 16, %2;"
                 :: "r"(dst), "l"(src), "r"(sz));
}
#define CP_COMMIT() asm volatile("cp.async.commit_group;" ::: "memory")
#define CP_WAIT3()  asm volatile("cp.async.wait_group 3;" ::: "memory")

__global__ __launch_bounds__(TPB, 4) void ncc_main_kernel(
    const float* __restrict__ I, const float* __restrict__ J,
    float* __restrict__ out)
{
    extern __shared__ __align__(16) float dyn[];
    float* warpsum = dyn + STG_FLOATS + 2 * RING_U64;

    const int tid  = threadIdx.x;
    const int lane = tid & 31;
    const int w    = tid >> 5;
    const int W0   = blockIdx.x * 512 + w * 128;
    const int Y0   = blockIdx.y * HS;
    const size_t imgoff = (size_t)blockIdx.z * IMG * IMG;

    uint32_t smem_u32;
    asm("{ .reg .u64 t; cvta.to.shared.u64 t, %1; cvt.u32.u64 %0, t; }"
        : "=r"(smem_u32) : "l"(dyn));

    // ---- cp.async chunk assignment: 34 float4 chunks per array per warp-row
    // (floats [W0-4, W0+132)); 68 chunks total across I then J.
    const int  cA   = lane;            // I chunks 0..31
    const int  gxA  = W0 - 4 + 4 * cA;
    const bool vAok = (gxA >= 0) && (gxA <= IMG - 4);
    const float* pbaseA = I + imgoff + (vAok ? gxA : 0);
    const uint32_t dstA0 = smem_u32 + ((w * 2 + 0) * SEGF + 4 * cA) * 4;

    const bool bIsI = lane < 2;        // chunks 32,33 are I; then J 0..29
    const int  cB   = bIsI ? (32 + lane) : (lane - 2);
    const int  gxB  = W0 - 4 + 4 * cB;
    const bool vBok = (gxB >= 0) && (gxB <= IMG - 4);
    const float* pbaseB = (bIsI ? I : J) + imgoff + (vBok ? gxB : 0);
    const uint32_t dstB0 = smem_u32 + ((w * 2 + (bIsI ? 0 : 1)) * SEGF + 4 * cB) * 4;

    const bool hasC = lane < 4;        // J chunks 30..33
    const int  cC   = 30 + lane;
    const int  gxC  = W0 - 4 + 4 * cC;
    const bool vCok = (gxC >= 0) && (gxC <= IMG - 4);
    const float* pbaseC = J + imgoff + (vCok ? gxC : 0);
    const uint32_t dstC0 = smem_u32 + ((w * 2 + 1) * SEGF + 4 * cC) * 4;

    const uint32_t BUFSTRIDE = NWB * 2 * SEGF * 4;   // 4352 bytes

    // ---- smem ring base (channels 2..4), 8B entry = 4 px as 2 x half2
    ull* ringT = (ull*)(dyn + STG_FLOATS) + tid;
#pragma unroll
    for (int s = 0; s < RSLOT; s++)
#pragma unroll
        for (int c = 0; c < NSC; c++)
            ringT[(s * NSC + c) * TPB] = 0ull;

    // ---- register ring (channels 0,1 = I, J): static indices only
    uint32_t rgl[2][RSLOT], rgh[2][RSLOT];
#pragma unroll
    for (int s = 0; s < RSLOT; s++) {
        rgl[0][s] = 0u; rgh[0][s] = 0u;
        rgl[1][s] = 0u; rgh[1][s] = 0u;
    }

    // ---- constants / state
    const ull NEG1   = pk2(-1.0f, -1.0f);
    const ull MINV81 = pk2(-1.0f / 81.0f, -1.0f / 81.0f);
    const ull EPS2   = pk2(1e-5f, 1e-5f);
    ull run[5][2];                        // [channel][pixel-pair]
#pragma unroll
    for (int c = 0; c < 5; c++) { run[c][0] = 0ull; run[c][1] = 0ull; }

    float acc = 0.f;
    float gn[2] = {0.f, 0.f}, gd[2] = {1.f, 1.f};

    // ---- stage: push rr -> input row Y0-4+rr (clamped addr, zero-fill OOB)
    auto stage = [&](int rr) {
        const int yin  = Y0 - 4 + rr;
        const bool yok = (unsigned)yin < (unsigned)IMG;
        const int  yc  = min(max(yin, 0), IMG - 1);
        const uint32_t off  = (uint32_t)yc << 10;
        const uint32_t boff = (uint32_t)(rr & (NBUF - 1)) * BUFSTRIDE;
        cp16(dstA0 + boff, pbaseA + off, (yok && vAok) ? 16u : 0u);
        cp16(dstB0 + boff, pbaseB + off, (yok && vBok) ? 16u : 0u);
        if (hasC)
            cp16(dstC0 + boff, pbaseC + off, (yok && vCok) ? 16u : 0u);
        CP_COMMIT();
    };

    // ---- per-push body; slot is a compile-time constant at every call site
    auto body = [&](int r, int slot, bool emitOK) {
        if (r + 3 < NPUSH) stage(r + 3);
        else               CP_COMMIT();
        CP_WAIT3();
        __syncwarp();

        // 12-float windows (4 px) from 3 LDS.128 per array
        const int buf = r & (NBUF - 1);
        const float4* fI4 = (const float4*)(dyn + (buf * NWB + w) * 2 * SEGF);
        const float4* fJ4 = fI4 + SEGF / 4;
        float4 ia = fI4[lane], ib = fI4[lane + 1], ic = fI4[lane + 2];
        float4 ja = fJ4[lane], jb = fJ4[lane + 1], jc = fJ4[lane + 2];
        float vi[12] = {ia.x, ia.y, ia.z, ia.w, ib.x, ib.y,
                        ib.z, ib.w, ic.x, ic.y, ic.z, ic.w};
        float vj[12] = {ja.x, ja.y, ja.z, ja.w, jb.x, jb.y,
                        jb.z, jb.w, jc.x, jc.y, jc.z, jc.w};

        // shared-core horizontal 9-tap sums for 4 px
        float h[5][4];
#pragma unroll
        for (int c = 0; c < 5; c++) {
            auto tap = [&](int k) -> float {
                return (c == 0) ? vi[k]
                     : (c == 1) ? vj[k]
                     : (c == 2) ? vi[k] * vi[k]
                     : (c == 3) ? vj[k] * vj[k]
                                : vi[k] * vj[k];
            };
            float core = tap(3) + tap(4) + tap(5) + tap(6) + tap(7) + tap(8);
            float m01  = core + tap(1) + tap(2);
            float m23  = core + tap(9) + tap(10);
            h[c][0] = m01 + tap(0);
            h[c][1] = m01 + tap(9);
            h[c][2] = m23 + tap(2);
            h[c][3] = m23 + tap(11);
        }

        // run update shared by both ring kinds
        auto upd = [&](int c, uint32_t olo, uint32_t ohi) {
            float2 o01 = __half22float2(*(__half2*)&olo);
            float2 o23 = __half22float2(*(__half2*)&ohi);
            ull od0 = pk2(o01.x, o01.y);
            ull od1 = pk2(o23.x, o23.y);
            ull h01 = pk2(h[c][0], h[c][1]);
            ull h23 = pk2(h[c][2], h[c][3]);
            FADD2(run[c][0], run[c][0], h01);
            FFMA2(run[c][0], od0, NEG1, run[c][0]);
            FADD2(run[c][1], run[c][1], h23);
            FFMA2(run[c][1], od1, NEG1, run[c][1]);
        };

        // channels 0,1: register ring (slot literal -> regs)
#pragma unroll
        for (int c = 0; c < 2; c++) {
            uint32_t olo = rgl[c][slot], ohi = rgh[c][slot];
            __half2 nlo = __floats2half2_rn(h[c][0], h[c][1]);
            __half2 nhi = __floats2half2_rn(h[c][2], h[c][3]);
            rgl[c][slot] = *(uint32_t*)&nlo;
            rgh[c][slot] = *(uint32_t*)&nhi;
            upd(c, olo, ohi);
        }
        // channels 2..4: smem ring
#pragma unroll
        for (int c = 2; c < 5; c++) {
            ull* rp  = ringT + (slot * NSC + (c - 2)) * TPB;
            ull  old = *rp;                               // LDS.64
            __half2 nlo = __floats2half2_rn(h[c][0], h[c][1]);
            __half2 nhi = __floats2half2_rn(h[c][2], h[c][3]);
            ull nw;
            asm("mov.b64 %0, {%1, %2};" : "=l"(nw)
                : "r"(*(uint32_t*)&nlo), "r"(*(uint32_t*)&nhi));
            *rp = nw;                                     // STS.64
            uint32_t olo, ohi;
            asm("mov.b64 {%0, %1}, %2;" : "=r"(olo), "=r"(ohi) : "l"(old));
            upd(c, olo, ohi);
        }

        // emit output row oy = Y0 + (r - 8)
        if (emitOK) {
            const int cnt = (r - 8) & 3;
#pragma unroll
            for (int p = 0; p < 2; p++) {
                ull t, u, cross2, iv2, jv2, n2, d2;
                FMUL2(t, run[0][p], MINV81);              // -si/81
                FFMA2(cross2, t, run[1][p], run[4][p]);   // SIJ - si*sj/81
                FFMA2(iv2,    t, run[0][p], run[2][p]);   // SI2 - si^2/81
                FMUL2(u, run[1][p], MINV81);              // -sj/81
                FFMA2(jv2,    u, run[1][p], run[3][p]);   // SJ2 - sj^2/81
                FMUL2(n2, cross2, cross2);
                FFMA2(d2, iv2, jv2, EPS2);
                float2 n = upk2(n2), d = upk2(d2);
                float rowN = fmaf(n.x, d.y, n.y * d.x);
                float rowD = d.x * d.y;
                if (cnt == 0) { gn[p] = rowN; gd[p] = rowD; }
                else { gn[p] = fmaf(gn[p], rowD, rowN * gd[p]); gd[p] *= rowD; }
                if (cnt == 3) {
                    float rc;
                    asm("rcp.approx.f32 %0, %1;" : "=f"(rc) : "f"(gd[p]));
                    acc = fmaf(gn[p], rc, acc);
                }
            }
        }
    };

    // ---- prologue: fill pipeline 3 deep, peel pushes 0..3 (slots 0..3)
    stage(0); stage(1); stage(2);
    body(0, 0, false);
    body(1, 1, false);
    body(2, 2, false);
    body(3, 3, false);

    // ---- main: 4 x unroll-9; slot = (4+s) % 9 compile-time
#pragma unroll 1
    for (int m = 0; m < 4; m++) {
#pragma unroll
        for (int s = 0; s < 9; s++) {
            const int r = 4 + 9 * m + s;
            const bool emitOK = (s >= 4) ? true : (m > 0);
            body(r, (4 + s) % 9, emitOK);
        }
    }

    // ---- block reduction + fused finalize
#pragma unroll
    for (int off = 16; off > 0; off >>= 1)
        acc += __shfl_down_sync(0xFFFFFFFFu, acc, off);
    if (lane == 0) warpsum[w] = acc;
    __syncthreads();
    if (tid == 0) {
        float v = warpsum[0] + warpsum[1] + warpsum[2] + warpsum[3];
        atomicAdd(&g_accum, (double)v);
        __threadfence();
        unsigned prev = atomicAdd(&g_cnt, 1u);
        if (prev == NBLK - 1) {               // last block finalizes + resets
            double tot = atomicAdd(&g_accum, 0.0);
            out[0] = (float)(tot / (double)((size_t)NB * IMG * IMG));
            g_accum = 0.0;
            g_cnt   = 0u;
        }
    }
}

extern "C" void kernel_launch(void* const* d_in, const int* in_sizes, int n_in,
                              void* d_out, int out_size) {
    const float* I = (const float*)d_in[0];
    const float* J = (const float*)d_in[1];
    float* out = (float*)d_out;

    cudaFuncSetAttribute(ncc_main_kernel,
                         cudaFuncAttributeMaxDynamicSharedMemorySize, SMEM_BYTES);
    dim3 grid(GX, GY, NB);
    ncc_main_kernel<<<grid, TPB, SMEM_BYTES>>>(I, J, out);
}